// round 15
// baseline (speedup 1.0000x reference)
#include <cuda_runtime.h>
#include <cuda_fp16.h>
#include <math.h>
#include <stdint.h>

#define BB   64
#define TT   128
#define HH   50
#define VV   8192
#define G4H  200
#define PP   64
#define MM   4096

typedef __half h16;

// ---------------- helpers ----------------
__device__ __forceinline__ uint32_t smem_u32(const void* p) {
    uint32_t a;
    asm("{ .reg .u64 t; cvta.to.shared.u64 t, %1; cvt.u32.u64 %0, t; }" : "=r"(a) : "l"(p));
    return a;
}
__device__ __forceinline__ void cp16(uint32_t saddr, const void* gptr) {
    asm volatile("cp.async.cg.shared.global [%0], [%1], 16;" :: "r"(saddr), "l"(gptr));
}
__device__ __forceinline__ void ldsm4(uint32_t& r0, uint32_t& r1, uint32_t& r2, uint32_t& r3, uint32_t addr) {
    asm volatile("ldmatrix.sync.aligned.m8n8.x4.shared.b16 {%0,%1,%2,%3}, [%4];"
                 : "=r"(r0), "=r"(r1), "=r"(r2), "=r"(r3) : "r"(addr));
}
__device__ __forceinline__ void ldsm4t(uint32_t& r0, uint32_t& r1, uint32_t& r2, uint32_t& r3, uint32_t addr) {
    asm volatile("ldmatrix.sync.aligned.m8n8.x4.trans.shared.b16 {%0,%1,%2,%3}, [%4];"
                 : "=r"(r0), "=r"(r1), "=r"(r2), "=r"(r3) : "r"(addr));
}
__device__ __forceinline__ void mma16816(float* c, const uint32_t* a, const uint32_t* b) {
    asm volatile("mma.sync.aligned.m16n8k16.row.col.f32.f16.f16.f32 "
                 "{%0,%1,%2,%3}, {%4,%5,%6,%7}, {%8,%9}, {%0,%1,%2,%3};"
                 : "+f"(c[0]), "+f"(c[1]), "+f"(c[2]), "+f"(c[3])
                 : "r"(a[0]), "r"(a[1]), "r"(a[2]), "r"(a[3]), "r"(b[0]), "r"(b[1]));
}
__device__ __forceinline__ float sigf(float x) { return 1.0f / (1.0f + expf(-x)); }

// ---------------- scratch globals ----------------
__device__ __align__(256) float g_Ewx[VV * G4H];
__device__ __align__(256) h16 g_pooled[MM * 64];
__device__ __align__(256) h16 g_W1p[64 * VV];                 // W1 zero-padded [64][V] fp16
__device__ __align__(256) h16 g_W1bh[(size_t)VV * VV];        // W1b fp16, native [K][N]
__device__ __align__(256) h16 g_W2h[(size_t)VV * VV];         // W2  fp16, native [K][N]
__device__ __align__(256) h16 g_x1[(size_t)MM * VV];
__device__ __align__(256) h16 g_x2[(size_t)MM * VV];

// ---------------- fused prep kernel (r14 proven) ----------------
#define NB_EWX  VV
#define NB_W1   ((64 * VV) / 2048)                 // 256
#define NB_CONV (((size_t)VV * VV) / 2048)         // 32768

__device__ __forceinline__ void convS_body(const float* __restrict__ W, h16* __restrict__ Wh,
                                           size_t i) {
    float4 a = *(const float4*)&W[i];
    float4 b = *(const float4*)&W[i + 4];
    __half2 h0 = __floats2half2_rn(a.x, a.y);
    __half2 h1 = __floats2half2_rn(a.z, a.w);
    __half2 h2 = __floats2half2_rn(b.x, b.y);
    __half2 h3 = __floats2half2_rn(b.z, b.w);
    uint4 pk;
    pk.x = *(uint32_t*)&h0; pk.y = *(uint32_t*)&h1;
    pk.z = *(uint32_t*)&h2; pk.w = *(uint32_t*)&h3;
    *(uint4*)&Wh[i] = pk;
}

__global__ void prep_kernel(const float* __restrict__ E, const float* __restrict__ Wx,
                            const float* __restrict__ bias, const float* __restrict__ W1,
                            const float* __restrict__ W1b, const float* __restrict__ W2) {
    __shared__ float e[HH];
    int b = blockIdx.x, tid = threadIdx.x;
    if (b < NB_EWX) {
        if (tid < HH) e[tid] = E[b * HH + tid];
        __syncthreads();
        if (tid < G4H) {
            float acc = bias[tid];
#pragma unroll
            for (int h = 0; h < HH; ++h) acc = fmaf(e[h], Wx[h * G4H + tid], acc);
            g_Ewx[(size_t)b * G4H + tid] = acc;
        }
    } else if (b < NB_EWX + NB_W1) {
        size_t i = (size_t)(b - NB_EWX) * 2048 + (size_t)tid * 8;
        if (i < (size_t)HH * VV) {
            convS_body(W1, g_W1p, i);
        } else {
            uint4 z = {0, 0, 0, 0};
            *(uint4*)&g_W1p[i] = z;
        }
    } else if (b < NB_EWX + NB_W1 + (int)NB_CONV) {
        size_t i = (size_t)(b - NB_EWX - NB_W1) * 2048 + (size_t)tid * 8;
        convS_body(W1b, g_W1bh, i);
    } else {
        size_t i = (size_t)(b - NB_EWX - NB_W1 - (int)NB_CONV) * 2048 + (size_t)tid * 8;
        convS_body(W2, g_W2h, i);
    }
}

// ---------------- LSTM scan + fused MaxPool(2), fp16 out (r13 proven) ----------------
__global__ void lstm_kernel(const int* __restrict__ inp, const float* __restrict__ U,
                            const float* __restrict__ rec_mask) {
    __shared__ float sU[4 * HH * HH];
    __shared__ float rm[G4H], hm[G4H], z[G4H];
    __shared__ __align__(16) float zbuf[2][G4H];
    __shared__ float h[HH], c[HH], hprev[HH];
    __shared__ int sidx[TT];
    int b = blockIdx.x, tid = threadIdx.x;

    for (int i = tid; i < 4 * HH * HH; i += 256) sU[i] = U[i];
    if (tid < TT) sidx[tid] = inp[b * TT + tid];
    if (tid < G4H) {
        int g = tid / HH, j = tid - g * HH;
        rm[tid] = rec_mask[((size_t)g * BB + b) * HH + j];
    }
    if (tid < HH) { h[tid] = 0.0f; c[tid] = 0.0f; hprev[tid] = 0.0f; }
    __syncthreads();

    uint32_t zb[2];
    zb[0] = smem_u32(&zbuf[0][0]);
    zb[1] = smem_u32(&zbuf[1][0]);

    if (tid < 50) cp16(zb[0] + tid * 16, g_Ewx + (size_t)sidx[0] * G4H + tid * 4);
    asm volatile("cp.async.commit_group;" ::: "memory");

    for (int t = 0; t < TT; ++t) {
        if (t + 1 < TT && tid < 50)
            cp16(zb[(t + 1) & 1] + tid * 16, g_Ewx + (size_t)sidx[t + 1] * G4H + tid * 4);
        asm volatile("cp.async.commit_group;" ::: "memory");
        asm volatile("cp.async.wait_group 1;" ::: "memory");

        if (tid < G4H) hm[tid] = h[tid % HH] * rm[tid];
        __syncthreads();
        if (tid < G4H) {
            int g = tid / HH, j = tid - g * HH;
            float acc = zbuf[t & 1][tid];
            const float* Ug = sU + g * HH * HH + j;
            const float* hg = hm + g * HH;
#pragma unroll
            for (int k = 0; k < HH; ++k) acc = fmaf(hg[k], Ug[k * HH], acc);
            z[tid] = acc;
        }
        __syncthreads();
        if (tid < HH) {
            float iv = sigf(z[tid]);
            float fv = sigf(z[HH + tid]);
            float gv = tanhf(z[2 * HH + tid]);
            float ov = sigf(z[3 * HH + tid]);
            float cn = fv * c[tid] + iv * gv;
            float hn = ov * tanhf(cn);
            c[tid] = cn;
            h[tid] = hn;
            if (t & 1) {
                g_pooled[((size_t)b * PP + (t >> 1)) * 64 + tid] = __float2half_rn(fmaxf(hprev[tid], hn));
            } else hprev[tid] = hn;
        } else if (tid < 64 && (t & 1)) {
            g_pooled[((size_t)b * PP + (t >> 1)) * 64 + tid] = __float2half_rn(0.0f);
        }
        __syncthreads();
    }
}

// ---------------- fp16 HMMA GEMM, CTA 256x128xBK32, 512 threads, 6-buffer ring ----------------
// NEW vs r14: two K-stages per barrier. wait_group 2 guarantees stages p,p+1 resident;
// one __syncthreads covers both; loads for p+4,p+5 issued after compute (validated ordering).
// B is row-major [K][N] fp16 consumed via ldmatrix.x4.trans (r14 proven layout).
#define GBM 256
#define GBN 128
#define BKH 32
#define RSA 80                        // A row stride: 64B data + 16B pad
#define RSBB 272                      // B row stride: 256B data + 16B pad
#define A_BYTES (GBM * RSA)           // 20480
#define B_BYTES (BKH * RSBB)          // 8704
#define STAGE (A_BYTES + B_BYTES)     // 29184
#define NST 6
#define GSMEM (NST * STAGE)           // 175104

template <int EPI>
__global__ void __launch_bounds__(512) hgemm(
    const h16* __restrict__ A, const h16* __restrict__ B, int K,
    const float* __restrict__ bias, const float* __restrict__ mask,
    h16* __restrict__ outh, float* __restrict__ outf) {
    extern __shared__ char smem[];
    uint32_t sb = smem_u32(smem);
    int tid = threadIdx.x, lid = tid & 31, wid = tid >> 5;
    int wm = wid >> 2, wn = wid & 3;   // 4x4 warp grid, warp tile 64x32

    // GROUP_M=8 rasterization
    const int NTN = VV / GBN;          // 64
    int pid = blockIdx.x;
    int npg = 8 * NTN;                 // 512
    int gid = pid / npg;
    int pm = gid * 8 + (pid % 8);
    int pn = (pid % npg) / 8;
    int bm = pm * GBM, bn = pn * GBN;

    int lrowA = tid >> 2, lchA = tid & 3;
    int lrowB = tid >> 4, lchB = tid & 15;
    const h16* gA = A + (size_t)bm * K;
    const h16* gBn = B + bn;

    uint32_t aoff = (uint32_t)((wm * 64 + (lid & 15)) * RSA + (lid >> 4) * 16);
    uint32_t boff = (uint32_t)((lid & 15) * RSBB + (wn * 32 + ((lid >> 4) << 3)) * 2);

    float acc[4][4][4];
#pragma unroll
    for (int i = 0; i < 4; ++i)
#pragma unroll
        for (int j = 0; j < 4; ++j)
#pragma unroll
            for (int q = 0; q < 4; ++q) acc[i][j][q] = 0.0f;

    int nk = K / BKH;                  // 2 or 256 — always even

    auto load = [&](int s, int buf) {
        uint32_t base = sb + (uint32_t)buf * STAGE;
        int k0 = s * BKH;
#pragma unroll
        for (int it = 0; it < 2; ++it) {
            int row = lrowA + it * 128;
            uint32_t so = (uint32_t)(row * RSA + lchA * 16);
            cp16(base + so, gA + (size_t)row * K + k0 + lchA * 8);
        }
        {
            uint32_t so = (uint32_t)(lrowB * RSBB + lchB * 16);
            cp16(base + A_BYTES + so, gBn + (size_t)(k0 + lrowB) * VV + lchB * 8);
        }
    };

    auto compute = [&](int buf) {
        uint32_t base = sb + (uint32_t)buf * STAGE;
        uint32_t Ab = base + aoff;
        uint32_t Bb = base + A_BYTES + boff;
#pragma unroll
        for (int tk = 0; tk < 2; ++tk) {
            uint32_t a[4][4], bfr[4][2];
#pragma unroll
            for (int mi = 0; mi < 4; ++mi)
                ldsm4(a[mi][0], a[mi][1], a[mi][2], a[mi][3], Ab + mi * (16 * RSA) + tk * 32);
            {
                uint32_t kbase = Bb + (uint32_t)tk * (16 * RSBB);
                uint32_t t0, t1, t2, t3;
                ldsm4t(t0, t1, t2, t3, kbase);
                bfr[0][0] = t0; bfr[0][1] = t1;
                bfr[1][0] = t2; bfr[1][1] = t3;
                ldsm4t(t0, t1, t2, t3, kbase + 32);
                bfr[2][0] = t0; bfr[2][1] = t1;
                bfr[3][0] = t2; bfr[3][1] = t3;
            }
#pragma unroll
            for (int mi = 0; mi < 4; ++mi)
#pragma unroll
                for (int nj = 0; nj < 4; ++nj) mma16816(acc[mi][nj], a[mi], bfr[nj]);
        }
    };

    // prologue: stages 0..3 into buffers 0..3 (4 commit groups; empty ones still committed)
#pragma unroll
    for (int i = 0; i < 4; ++i) {
        if (i < nk) load(i, i);
        asm volatile("cp.async.commit_group;" ::: "memory");
    }

    int bufp = 0;                       // buffer of stage p
    for (int p = 0; p < nk; p += 2) {
        asm volatile("cp.async.wait_group 2;" ::: "memory");
        __syncthreads();
        int b1i = (bufp + 1 >= NST) ? bufp + 1 - NST : bufp + 1;
        compute(bufp);
        compute(b1i);
        int l0 = (bufp + 4 >= NST) ? bufp + 4 - NST : bufp + 4;
        int l1 = (bufp + 5 >= NST) ? bufp + 5 - NST : bufp + 5;
        if (p + 4 < nk) load(p + 4, l0);
        asm volatile("cp.async.commit_group;" ::: "memory");
        if (p + 5 < nk) load(p + 5, l1);
        asm volatile("cp.async.commit_group;" ::: "memory");
        bufp = (bufp + 2 >= NST) ? bufp + 2 - NST : bufp + 2;
    }

    // epilogue
#pragma unroll
    for (int mi = 0; mi < 4; ++mi) {
        int rbase = bm + wm * 64 + mi * 16 + (lid >> 2);
#pragma unroll
        for (int nj = 0; nj < 4; ++nj) {
            int cn = bn + wn * 32 + nj * 8 + (lid & 3) * 2;
            float2 bv = *(const float2*)&bias[cn];
#pragma unroll
            for (int hh = 0; hh < 2; ++hh) {
                int row = rbase + hh * 8;
                size_t o = (size_t)row * VV + cn;
                float v0 = acc[mi][nj][hh * 2 + 0] + bv.x;
                float v1 = acc[mi][nj][hh * 2 + 1] + bv.y;
                if (EPI == 0) {
                    float2 mk = *(const float2*)&mask[o];
                    v0 = fmaxf(v0, 0.0f) * mk.x;
                    v1 = fmaxf(v1, 0.0f) * mk.y;
                    *(__half2*)(outh + o) = __floats2half2_rn(v0, v1);
                } else {
                    float2 rr;
                    rr.x = sigf(v0); rr.y = sigf(v1);
                    *(float2*)(outf + o) = rr;
                }
            }
        }
    }
}

// ---------------- launch (serial, proven ordering) ----------------
extern "C" void kernel_launch(void* const* d_in, const int* in_sizes, int n_in,
                              void* d_out, int out_size) {
    const int*   inp      = (const int*)  d_in[0];
    const float* E        = (const float*)d_in[1];
    const float* Wx       = (const float*)d_in[2];
    const float* U        = (const float*)d_in[3];
    const float* bb       = (const float*)d_in[4];
    const float* W1       = (const float*)d_in[5];
    const float* b1       = (const float*)d_in[6];
    const float* W1b      = (const float*)d_in[7];
    const float* W2       = (const float*)d_in[8];
    const float* b2       = (const float*)d_in[9];
    const float* rec_mask = (const float*)d_in[10];
    const float* dmask1   = (const float*)d_in[11];
    const float* dmask2   = (const float*)d_in[12];
    float* out = (float*)d_out;

    void *p_pooled, *p_w1p, *p_wbh, *p_w2h, *p_x1, *p_x2;
    cudaGetSymbolAddress(&p_pooled, g_pooled);
    cudaGetSymbolAddress(&p_w1p, g_W1p);
    cudaGetSymbolAddress(&p_wbh, g_W1bh);
    cudaGetSymbolAddress(&p_w2h, g_W2h);
    cudaGetSymbolAddress(&p_x1, g_x1);
    cudaGetSymbolAddress(&p_x2, g_x2);

    cudaFuncSetAttribute(hgemm<0>, cudaFuncAttributeMaxDynamicSharedMemorySize, GSMEM);
    cudaFuncSetAttribute(hgemm<1>, cudaFuncAttributeMaxDynamicSharedMemorySize, GSMEM);

    prep_kernel<<<NB_EWX + NB_W1 + 2 * (int)NB_CONV, 256>>>(E, Wx, bb, W1, W1b, W2);
    lstm_kernel<<<BB, 256>>>(inp, U, rec_mask);

    const int grid = (MM / GBM) * (VV / GBN);   // 16 * 64 = 1024
    hgemm<0><<<grid, 512, GSMEM>>>((const h16*)p_pooled, (const h16*)p_w1p, 64,
                                   b1, dmask1, (h16*)p_x1, nullptr);
    hgemm<0><<<grid, 512, GSMEM>>>((const h16*)p_x1, (const h16*)p_wbh, VV,
                                   b1, dmask2, (h16*)p_x2, nullptr);
    hgemm<1><<<grid, 512, GSMEM>>>((const h16*)p_x2, (const h16*)p_w2h, VV,
                                   b2, nullptr, nullptr, out);
}

// round 16
// speedup vs baseline: 1.0802x; 1.0802x over previous
#include <cuda_runtime.h>
#include <cuda_fp16.h>
#include <math.h>
#include <stdint.h>

#define BB   64
#define TT   128
#define HH   50
#define VV   8192
#define G4H  200
#define PP   64
#define MM   4096

typedef __half h16;

// ---------------- helpers ----------------
__device__ __forceinline__ uint32_t smem_u32(const void* p) {
    uint32_t a;
    asm("{ .reg .u64 t; cvta.to.shared.u64 t, %1; cvt.u32.u64 %0, t; }" : "=r"(a) : "l"(p));
    return a;
}
__device__ __forceinline__ void cp16(uint32_t saddr, const void* gptr) {
    asm volatile("cp.async.cg.shared.global [%0], [%1], 16;" :: "r"(saddr), "l"(gptr));
}
__device__ __forceinline__ void ldsm4(uint32_t& r0, uint32_t& r1, uint32_t& r2, uint32_t& r3, uint32_t addr) {
    asm volatile("ldmatrix.sync.aligned.m8n8.x4.shared.b16 {%0,%1,%2,%3}, [%4];"
                 : "=r"(r0), "=r"(r1), "=r"(r2), "=r"(r3) : "r"(addr));
}
__device__ __forceinline__ void ldsm4t(uint32_t& r0, uint32_t& r1, uint32_t& r2, uint32_t& r3, uint32_t addr) {
    asm volatile("ldmatrix.sync.aligned.m8n8.x4.trans.shared.b16 {%0,%1,%2,%3}, [%4];"
                 : "=r"(r0), "=r"(r1), "=r"(r2), "=r"(r3) : "r"(addr));
}
__device__ __forceinline__ void mma16816(float* c, const uint32_t* a, const uint32_t* b) {
    asm volatile("mma.sync.aligned.m16n8k16.row.col.f32.f16.f16.f32 "
                 "{%0,%1,%2,%3}, {%4,%5,%6,%7}, {%8,%9}, {%0,%1,%2,%3};"
                 : "+f"(c[0]), "+f"(c[1]), "+f"(c[2]), "+f"(c[3])
                 : "r"(a[0]), "r"(a[1]), "r"(a[2]), "r"(a[3]), "r"(b[0]), "r"(b[1]));
}
__device__ __forceinline__ float sigf(float x) { return 1.0f / (1.0f + expf(-x)); }

// ---------------- scratch globals ----------------
__device__ __align__(256) float g_Ewx[VV * G4H];
__device__ __align__(256) h16 g_pooled[MM * 64];
__device__ __align__(256) h16 g_W1p[64 * VV];                 // W1 zero-padded [64][V] fp16
__device__ __align__(256) h16 g_W1bh[(size_t)VV * VV];        // W1b fp16, native [K][N]
__device__ __align__(256) h16 g_W2h[(size_t)VV * VV];         // W2  fp16, native [K][N]
__device__ __align__(256) h16 g_x1[(size_t)MM * VV];
__device__ __align__(256) h16 g_x2[(size_t)MM * VV];

// ---------------- fused prep kernel (r14 proven) ----------------
#define NB_EWX  VV
#define NB_W1   ((64 * VV) / 2048)                 // 256
#define NB_CONV (((size_t)VV * VV) / 2048)         // 32768

__device__ __forceinline__ void convS_body(const float* __restrict__ W, h16* __restrict__ Wh,
                                           size_t i) {
    float4 a = *(const float4*)&W[i];
    float4 b = *(const float4*)&W[i + 4];
    __half2 h0 = __floats2half2_rn(a.x, a.y);
    __half2 h1 = __floats2half2_rn(a.z, a.w);
    __half2 h2 = __floats2half2_rn(b.x, b.y);
    __half2 h3 = __floats2half2_rn(b.z, b.w);
    uint4 pk;
    pk.x = *(uint32_t*)&h0; pk.y = *(uint32_t*)&h1;
    pk.z = *(uint32_t*)&h2; pk.w = *(uint32_t*)&h3;
    *(uint4*)&Wh[i] = pk;
}

__global__ void prep_kernel(const float* __restrict__ E, const float* __restrict__ Wx,
                            const float* __restrict__ bias, const float* __restrict__ W1,
                            const float* __restrict__ W1b, const float* __restrict__ W2) {
    __shared__ float e[HH];
    int b = blockIdx.x, tid = threadIdx.x;
    if (b < NB_EWX) {
        if (tid < HH) e[tid] = E[b * HH + tid];
        __syncthreads();
        if (tid < G4H) {
            float acc = bias[tid];
#pragma unroll
            for (int h = 0; h < HH; ++h) acc = fmaf(e[h], Wx[h * G4H + tid], acc);
            g_Ewx[(size_t)b * G4H + tid] = acc;
        }
    } else if (b < NB_EWX + NB_W1) {
        size_t i = (size_t)(b - NB_EWX) * 2048 + (size_t)tid * 8;
        if (i < (size_t)HH * VV) {
            convS_body(W1, g_W1p, i);
        } else {
            uint4 z = {0, 0, 0, 0};
            *(uint4*)&g_W1p[i] = z;
        }
    } else if (b < NB_EWX + NB_W1 + (int)NB_CONV) {
        size_t i = (size_t)(b - NB_EWX - NB_W1) * 2048 + (size_t)tid * 8;
        convS_body(W1b, g_W1bh, i);
    } else {
        size_t i = (size_t)(b - NB_EWX - NB_W1 - (int)NB_CONV) * 2048 + (size_t)tid * 8;
        convS_body(W2, g_W2h, i);
    }
}

// ---------------- LSTM scan + fused MaxPool(2), fp16 out (r13 proven) ----------------
__global__ void lstm_kernel(const int* __restrict__ inp, const float* __restrict__ U,
                            const float* __restrict__ rec_mask) {
    __shared__ float sU[4 * HH * HH];
    __shared__ float rm[G4H], hm[G4H], z[G4H];
    __shared__ __align__(16) float zbuf[2][G4H];
    __shared__ float h[HH], c[HH], hprev[HH];
    __shared__ int sidx[TT];
    int b = blockIdx.x, tid = threadIdx.x;

    for (int i = tid; i < 4 * HH * HH; i += 256) sU[i] = U[i];
    if (tid < TT) sidx[tid] = inp[b * TT + tid];
    if (tid < G4H) {
        int g = tid / HH, j = tid - g * HH;
        rm[tid] = rec_mask[((size_t)g * BB + b) * HH + j];
    }
    if (tid < HH) { h[tid] = 0.0f; c[tid] = 0.0f; hprev[tid] = 0.0f; }
    __syncthreads();

    uint32_t zb[2];
    zb[0] = smem_u32(&zbuf[0][0]);
    zb[1] = smem_u32(&zbuf[1][0]);

    if (tid < 50) cp16(zb[0] + tid * 16, g_Ewx + (size_t)sidx[0] * G4H + tid * 4);
    asm volatile("cp.async.commit_group;" ::: "memory");

    for (int t = 0; t < TT; ++t) {
        if (t + 1 < TT && tid < 50)
            cp16(zb[(t + 1) & 1] + tid * 16, g_Ewx + (size_t)sidx[t + 1] * G4H + tid * 4);
        asm volatile("cp.async.commit_group;" ::: "memory");
        asm volatile("cp.async.wait_group 1;" ::: "memory");

        if (tid < G4H) hm[tid] = h[tid % HH] * rm[tid];
        __syncthreads();
        if (tid < G4H) {
            int g = tid / HH, j = tid - g * HH;
            float acc = zbuf[t & 1][tid];
            const float* Ug = sU + g * HH * HH + j;
            const float* hg = hm + g * HH;
#pragma unroll
            for (int k = 0; k < HH; ++k) acc = fmaf(hg[k], Ug[k * HH], acc);
            z[tid] = acc;
        }
        __syncthreads();
        if (tid < HH) {
            float iv = sigf(z[tid]);
            float fv = sigf(z[HH + tid]);
            float gv = tanhf(z[2 * HH + tid]);
            float ov = sigf(z[3 * HH + tid]);
            float cn = fv * c[tid] + iv * gv;
            float hn = ov * tanhf(cn);
            c[tid] = cn;
            h[tid] = hn;
            if (t & 1) {
                g_pooled[((size_t)b * PP + (t >> 1)) * 64 + tid] = __float2half_rn(fmaxf(hprev[tid], hn));
            } else hprev[tid] = hn;
        } else if (tid < 64 && (t & 1)) {
            g_pooled[((size_t)b * PP + (t >> 1)) * 64 + tid] = __float2half_rn(0.0f);
        }
        __syncthreads();
    }
}

// ---------------- fp16 HMMA GEMM, CTA 256x128xBK32, 512 threads, 6-buffer ring ----------------
// Two K-stages per barrier with COMPILE-TIME buffer indices (period-3 unroll of the ring).
// B is row-major [K][N] fp16 via ldmatrix.x4.trans (r14 proven). Loads after compute.
#define GBM 256
#define GBN 128
#define BKH 32
#define RSA 80                        // A row stride: 64B data + 16B pad
#define RSBB 272                      // B row stride: 256B data + 16B pad
#define A_BYTES (GBM * RSA)           // 20480
#define B_BYTES (BKH * RSBB)          // 8704
#define STAGE (A_BYTES + B_BYTES)     // 29184
#define NST 6
#define GSMEM (NST * STAGE)           // 175104

template <int EPI>
__global__ void __launch_bounds__(512) hgemm(
    const h16* __restrict__ A, const h16* __restrict__ B, int K,
    const float* __restrict__ bias, const float* __restrict__ mask,
    h16* __restrict__ outh, float* __restrict__ outf) {
    extern __shared__ char smem[];
    uint32_t sb = smem_u32(smem);
    int tid = threadIdx.x, lid = tid & 31, wid = tid >> 5;
    int wm = wid >> 2, wn = wid & 3;   // 4x4 warp grid, warp tile 64x32

    // GROUP_M=8 rasterization
    const int NTN = VV / GBN;          // 64
    int pid = blockIdx.x;
    int npg = 8 * NTN;                 // 512
    int gid = pid / npg;
    int pm = gid * 8 + (pid % 8);
    int pn = (pid % npg) / 8;
    int bm = pm * GBM, bn = pn * GBN;

    int lrowA = tid >> 2, lchA = tid & 3;
    int lrowB = tid >> 4, lchB = tid & 15;
    const h16* gA = A + (size_t)bm * K;
    const h16* gBn = B + bn;

    uint32_t aoff = (uint32_t)((wm * 64 + (lid & 15)) * RSA + (lid >> 4) * 16);
    uint32_t boff = (uint32_t)((lid & 15) * RSBB + (wn * 32 + ((lid >> 4) << 3)) * 2);

    float acc[4][4][4];
#pragma unroll
    for (int i = 0; i < 4; ++i)
#pragma unroll
        for (int j = 0; j < 4; ++j)
#pragma unroll
            for (int q = 0; q < 4; ++q) acc[i][j][q] = 0.0f;

    int nk = K / BKH;                  // 2 or 256 — always even

    auto load = [&](int s, const int buf) {
        uint32_t base = sb + (uint32_t)(buf * STAGE);
        int k0 = s * BKH;
#pragma unroll
        for (int it = 0; it < 2; ++it) {
            int row = lrowA + it * 128;
            uint32_t so = (uint32_t)(row * RSA + lchA * 16);
            cp16(base + so, gA + (size_t)row * K + k0 + lchA * 8);
        }
        {
            uint32_t so = (uint32_t)(lrowB * RSBB + lchB * 16);
            cp16(base + A_BYTES + so, gBn + (size_t)(k0 + lrowB) * VV + lchB * 8);
        }
    };

    auto compute = [&](const int buf) {
        uint32_t base = sb + (uint32_t)(buf * STAGE);
        uint32_t Ab = base + aoff;
        uint32_t Bb = base + A_BYTES + boff;
#pragma unroll
        for (int tk = 0; tk < 2; ++tk) {
            uint32_t a[4][4], bfr[4][2];
#pragma unroll
            for (int mi = 0; mi < 4; ++mi)
                ldsm4(a[mi][0], a[mi][1], a[mi][2], a[mi][3], Ab + mi * (16 * RSA) + tk * 32);
            {
                uint32_t kbase = Bb + (uint32_t)tk * (16 * RSBB);
                uint32_t t0, t1, t2, t3;
                ldsm4t(t0, t1, t2, t3, kbase);
                bfr[0][0] = t0; bfr[0][1] = t1;
                bfr[1][0] = t2; bfr[1][1] = t3;
                ldsm4t(t0, t1, t2, t3, kbase + 32);
                bfr[2][0] = t0; bfr[2][1] = t1;
                bfr[3][0] = t2; bfr[3][1] = t3;
            }
#pragma unroll
            for (int mi = 0; mi < 4; ++mi)
#pragma unroll
                for (int nj = 0; nj < 4; ++nj) mma16816(acc[mi][nj], a[mi], bfr[nj]);
        }
    };

    // one barrier per TWO stages; cb0/cb1/lb0/lb1 are literal constants at every call site
    auto step = [&](int p, const int cb0, const int cb1, const int lb0, const int lb1) {
        asm volatile("cp.async.wait_group 2;" ::: "memory");
        __syncthreads();
        compute(cb0);
        compute(cb1);
        if (p + 4 < nk) load(p + 4, lb0);
        asm volatile("cp.async.commit_group;" ::: "memory");
        if (p + 5 < nk) load(p + 5, lb1);
        asm volatile("cp.async.commit_group;" ::: "memory");
    };

    // prologue: stages 0..3 into buffers 0..3 (constant indices; empty groups still committed)
    if (0 < nk) load(0, 0);
    asm volatile("cp.async.commit_group;" ::: "memory");
    if (1 < nk) load(1, 1);
    asm volatile("cp.async.commit_group;" ::: "memory");
    if (2 < nk) load(2, 2);
    asm volatile("cp.async.commit_group;" ::: "memory");
    if (3 < nk) load(3, 3);
    asm volatile("cp.async.commit_group;" ::: "memory");

    int p = 0;
    // period-3 ring: (0,1)->(2,3)->(4,5), loads into (4,5)->(0,1)->(2,3)
    while (p + 6 <= nk) {
        step(p,     0, 1, 4, 5);
        step(p + 2, 2, 3, 0, 1);
        step(p + 4, 4, 5, 2, 3);
        p += 6;
    }
    // remainder: at most 2 barrier-iters; p is a multiple of 6 here so buffers are fixed
    if (p < nk) { step(p, 0, 1, 4, 5); p += 2; }
    if (p < nk) { step(p, 2, 3, 0, 1); p += 2; }

    // epilogue
#pragma unroll
    for (int mi = 0; mi < 4; ++mi) {
        int rbase = bm + wm * 64 + mi * 16 + (lid >> 2);
#pragma unroll
        for (int nj = 0; nj < 4; ++nj) {
            int cn = bn + wn * 32 + nj * 8 + (lid & 3) * 2;
            float2 bv = *(const float2*)&bias[cn];
#pragma unroll
            for (int hh = 0; hh < 2; ++hh) {
                int row = rbase + hh * 8;
                size_t o = (size_t)row * VV + cn;
                float v0 = acc[mi][nj][hh * 2 + 0] + bv.x;
                float v1 = acc[mi][nj][hh * 2 + 1] + bv.y;
                if (EPI == 0) {
                    float2 mk = *(const float2*)&mask[o];
                    v0 = fmaxf(v0, 0.0f) * mk.x;
                    v1 = fmaxf(v1, 0.0f) * mk.y;
                    *(__half2*)(outh + o) = __floats2half2_rn(v0, v1);
                } else {
                    float2 rr;
                    rr.x = sigf(v0); rr.y = sigf(v1);
                    *(float2*)(outf + o) = rr;
                }
            }
        }
    }
}

// ---------------- launch (serial, proven ordering) ----------------
extern "C" void kernel_launch(void* const* d_in, const int* in_sizes, int n_in,
                              void* d_out, int out_size) {
    const int*   inp      = (const int*)  d_in[0];
    const float* E        = (const float*)d_in[1];
    const float* Wx       = (const float*)d_in[2];
    const float* U        = (const float*)d_in[3];
    const float* bb       = (const float*)d_in[4];
    const float* W1       = (const float*)d_in[5];
    const float* b1       = (const float*)d_in[6];
    const float* W1b      = (const float*)d_in[7];
    const float* W2       = (const float*)d_in[8];
    const float* b2       = (const float*)d_in[9];
    const float* rec_mask = (const float*)d_in[10];
    const float* dmask1   = (const float*)d_in[11];
    const float* dmask2   = (const float*)d_in[12];
    float* out = (float*)d_out;

    void *p_pooled, *p_w1p, *p_wbh, *p_w2h, *p_x1, *p_x2;
    cudaGetSymbolAddress(&p_pooled, g_pooled);
    cudaGetSymbolAddress(&p_w1p, g_W1p);
    cudaGetSymbolAddress(&p_wbh, g_W1bh);
    cudaGetSymbolAddress(&p_w2h, g_W2h);
    cudaGetSymbolAddress(&p_x1, g_x1);
    cudaGetSymbolAddress(&p_x2, g_x2);

    cudaFuncSetAttribute(hgemm<0>, cudaFuncAttributeMaxDynamicSharedMemorySize, GSMEM);
    cudaFuncSetAttribute(hgemm<1>, cudaFuncAttributeMaxDynamicSharedMemorySize, GSMEM);

    prep_kernel<<<NB_EWX + NB_W1 + 2 * (int)NB_CONV, 256>>>(E, Wx, bb, W1, W1b, W2);
    lstm_kernel<<<BB, 256>>>(inp, U, rec_mask);

    const int grid = (MM / GBM) * (VV / GBN);   // 16 * 64 = 1024
    hgemm<0><<<grid, 512, GSMEM>>>((const h16*)p_pooled, (const h16*)p_w1p, 64,
                                   b1, dmask1, (h16*)p_x1, nullptr);
    hgemm<0><<<grid, 512, GSMEM>>>((const h16*)p_x1, (const h16*)p_wbh, VV,
                                   b1, dmask2, (h16*)p_x2, nullptr);
    hgemm<1><<<grid, 512, GSMEM>>>((const h16*)p_x2, (const h16*)p_w2h, VV,
                                   b2, nullptr, nullptr, out);
}

// round 17
// speedup vs baseline: 1.2094x; 1.1196x over previous
#include <cuda_runtime.h>
#include <cuda_fp16.h>
#include <math.h>
#include <stdint.h>

#define BB   64
#define TT   128
#define HH   50
#define VV   8192
#define G4H  200
#define PP   64
#define MM   4096

typedef __half h16;

// ---------------- helpers ----------------
__device__ __forceinline__ uint32_t smem_u32(const void* p) {
    uint32_t a;
    asm("{ .reg .u64 t; cvta.to.shared.u64 t, %1; cvt.u32.u64 %0, t; }" : "=r"(a) : "l"(p));
    return a;
}
__device__ __forceinline__ void cp16(uint32_t saddr, const void* gptr) {
    asm volatile("cp.async.cg.shared.global [%0], [%1], 16;" :: "r"(saddr), "l"(gptr));
}
__device__ __forceinline__ void ldsm4(uint32_t& r0, uint32_t& r1, uint32_t& r2, uint32_t& r3, uint32_t addr) {
    asm volatile("ldmatrix.sync.aligned.m8n8.x4.shared.b16 {%0,%1,%2,%3}, [%4];"
                 : "=r"(r0), "=r"(r1), "=r"(r2), "=r"(r3) : "r"(addr));
}
__device__ __forceinline__ void ldsm4t(uint32_t& r0, uint32_t& r1, uint32_t& r2, uint32_t& r3, uint32_t addr) {
    asm volatile("ldmatrix.sync.aligned.m8n8.x4.trans.shared.b16 {%0,%1,%2,%3}, [%4];"
                 : "=r"(r0), "=r"(r1), "=r"(r2), "=r"(r3) : "r"(addr));
}
__device__ __forceinline__ void mma16816(float* c, const uint32_t* a, const uint32_t* b) {
    asm volatile("mma.sync.aligned.m16n8k16.row.col.f32.f16.f16.f32 "
                 "{%0,%1,%2,%3}, {%4,%5,%6,%7}, {%8,%9}, {%0,%1,%2,%3};"
                 : "+f"(c[0]), "+f"(c[1]), "+f"(c[2]), "+f"(c[3])
                 : "r"(a[0]), "r"(a[1]), "r"(a[2]), "r"(a[3]), "r"(b[0]), "r"(b[1]));
}
__device__ __forceinline__ float sigf(float x) { return 1.0f / (1.0f + expf(-x)); }

// ---------------- scratch globals ----------------
__device__ __align__(256) float g_Ewx[VV * G4H];
__device__ __align__(256) h16 g_pooled[MM * 64];
__device__ __align__(256) h16 g_W1p[64 * VV];                 // W1 zero-padded [64][V] fp16
__device__ __align__(256) h16 g_W1bh[(size_t)VV * VV];        // W1b fp16, native [K][N]
__device__ __align__(256) h16 g_W2h[(size_t)VV * VV];         // W2  fp16, native [K][N]
__device__ __align__(256) h16 g_x1[(size_t)MM * VV];
__device__ __align__(256) h16 g_x2[(size_t)MM * VV];

// ---------------- fused prep kernel ----------------
// blocks [0, 4096):          ewx: 2 vocab rows per block (Wx value reused for both rows)
// blocks [4096, 4352):       W1 [50,V] -> [64,V] fp16 (copy + zero pad)
// blocks [4352, +32768):     W1b fp32 -> fp16 streaming convert
// blocks [.., +32768):       W2  fp32 -> fp16 streaming convert
#define NB_EWX  (VV / 2)
#define NB_W1   ((64 * VV) / 2048)                 // 256
#define NB_CONV (((size_t)VV * VV) / 2048)         // 32768

__device__ __forceinline__ void convS_body(const float* __restrict__ W, h16* __restrict__ Wh,
                                           size_t i) {
    float4 a = *(const float4*)&W[i];
    float4 b = *(const float4*)&W[i + 4];
    __half2 h0 = __floats2half2_rn(a.x, a.y);
    __half2 h1 = __floats2half2_rn(a.z, a.w);
    __half2 h2 = __floats2half2_rn(b.x, b.y);
    __half2 h3 = __floats2half2_rn(b.z, b.w);
    uint4 pk;
    pk.x = *(uint32_t*)&h0; pk.y = *(uint32_t*)&h1;
    pk.z = *(uint32_t*)&h2; pk.w = *(uint32_t*)&h3;
    *(uint4*)&Wh[i] = pk;
}

__global__ void prep_kernel(const float* __restrict__ E, const float* __restrict__ Wx,
                            const float* __restrict__ bias, const float* __restrict__ W1,
                            const float* __restrict__ W1b, const float* __restrict__ W2) {
    __shared__ float e0[HH], e1[HH];
    int b = blockIdx.x, tid = threadIdx.x;
    if (b < NB_EWX) {
        int v0 = b * 2, v1 = b * 2 + 1;
        if (tid < HH) {
            e0[tid] = E[v0 * HH + tid];
            e1[tid] = E[v1 * HH + tid];
        }
        __syncthreads();
        if (tid < G4H) {
            float bv = bias[tid];
            float a0 = bv, a1 = bv;
#pragma unroll
            for (int h = 0; h < HH; ++h) {
                float w = Wx[h * G4H + tid];
                a0 = fmaf(e0[h], w, a0);
                a1 = fmaf(e1[h], w, a1);
            }
            g_Ewx[(size_t)v0 * G4H + tid] = a0;
            g_Ewx[(size_t)v1 * G4H + tid] = a1;
        }
    } else if (b < NB_EWX + NB_W1) {
        size_t i = (size_t)(b - NB_EWX) * 2048 + (size_t)tid * 8;
        if (i < (size_t)HH * VV) {
            convS_body(W1, g_W1p, i);
        } else {
            uint4 z = {0, 0, 0, 0};
            *(uint4*)&g_W1p[i] = z;
        }
    } else if (b < NB_EWX + NB_W1 + (int)NB_CONV) {
        size_t i = (size_t)(b - NB_EWX - NB_W1) * 2048 + (size_t)tid * 8;
        convS_body(W1b, g_W1bh, i);
    } else {
        size_t i = (size_t)(b - NB_EWX - NB_W1 - (int)NB_CONV) * 2048 + (size_t)tid * 8;
        convS_body(W2, g_W2h, i);
    }
}

// ---------------- LSTM scan + fused MaxPool(2), fp16 out (r13 proven) ----------------
__global__ void lstm_kernel(const int* __restrict__ inp, const float* __restrict__ U,
                            const float* __restrict__ rec_mask) {
    __shared__ float sU[4 * HH * HH];
    __shared__ float rm[G4H], hm[G4H], z[G4H];
    __shared__ __align__(16) float zbuf[2][G4H];
    __shared__ float h[HH], c[HH], hprev[HH];
    __shared__ int sidx[TT];
    int b = blockIdx.x, tid = threadIdx.x;

    for (int i = tid; i < 4 * HH * HH; i += 256) sU[i] = U[i];
    if (tid < TT) sidx[tid] = inp[b * TT + tid];
    if (tid < G4H) {
        int g = tid / HH, j = tid - g * HH;
        rm[tid] = rec_mask[((size_t)g * BB + b) * HH + j];
    }
    if (tid < HH) { h[tid] = 0.0f; c[tid] = 0.0f; hprev[tid] = 0.0f; }
    __syncthreads();

    uint32_t zb[2];
    zb[0] = smem_u32(&zbuf[0][0]);
    zb[1] = smem_u32(&zbuf[1][0]);

    if (tid < 50) cp16(zb[0] + tid * 16, g_Ewx + (size_t)sidx[0] * G4H + tid * 4);
    asm volatile("cp.async.commit_group;" ::: "memory");

    for (int t = 0; t < TT; ++t) {
        if (t + 1 < TT && tid < 50)
            cp16(zb[(t + 1) & 1] + tid * 16, g_Ewx + (size_t)sidx[t + 1] * G4H + tid * 4);
        asm volatile("cp.async.commit_group;" ::: "memory");
        asm volatile("cp.async.wait_group 1;" ::: "memory");

        if (tid < G4H) hm[tid] = h[tid % HH] * rm[tid];
        __syncthreads();
        if (tid < G4H) {
            int g = tid / HH, j = tid - g * HH;
            float acc = zbuf[t & 1][tid];
            const float* Ug = sU + g * HH * HH + j;
            const float* hg = hm + g * HH;
#pragma unroll
            for (int k = 0; k < HH; ++k) acc = fmaf(hg[k], Ug[k * HH], acc);
            z[tid] = acc;
        }
        __syncthreads();
        if (tid < HH) {
            float iv = sigf(z[tid]);
            float fv = sigf(z[HH + tid]);
            float gv = tanhf(z[2 * HH + tid]);
            float ov = sigf(z[3 * HH + tid]);
            float cn = fv * c[tid] + iv * gv;
            float hn = ov * tanhf(cn);
            c[tid] = cn;
            h[tid] = hn;
            if (t & 1) {
                g_pooled[((size_t)b * PP + (t >> 1)) * 64 + tid] = __float2half_rn(fmaxf(hprev[tid], hn));
            } else hprev[tid] = hn;
        } else if (tid < 64 && (t & 1)) {
            g_pooled[((size_t)b * PP + (t >> 1)) * 64 + tid] = __float2half_rn(0.0f);
        }
        __syncthreads();
    }
}

// ---------------- fp16 HMMA GEMM (r14 proven, byte-identical) ----------------
// CTA 256x128xBK32, 512 threads, 4-stage ring, wait_group 2, loads after compute.
// B row-major [K][N] fp16 via ldmatrix.x4.trans.
#define GBM 256
#define GBN 128
#define BKH 32
#define RSA 80                        // A row stride: 64B data + 16B pad
#define RSBB 272                      // B row stride: 256B data + 16B pad
#define A_BYTES (GBM * RSA)           // 20480
#define B_BYTES (BKH * RSBB)          // 8704
#define STAGE (A_BYTES + B_BYTES)     // 29184
#define GSMEM (4 * STAGE)             // 116736

template <int EPI>
__global__ void __launch_bounds__(512) hgemm(
    const h16* __restrict__ A, const h16* __restrict__ B, int K,
    const float* __restrict__ bias, const float* __restrict__ mask,
    h16* __restrict__ outh, float* __restrict__ outf) {
    extern __shared__ char smem[];
    uint32_t sb = smem_u32(smem);
    int tid = threadIdx.x, lid = tid & 31, wid = tid >> 5;
    int wm = wid >> 2, wn = wid & 3;   // 4x4 warp grid, warp tile 64x32

    // GROUP_M=8 rasterization
    const int NTN = VV / GBN;          // 64
    int pid = blockIdx.x;
    int npg = 8 * NTN;                 // 512
    int gid = pid / npg;
    int pm = gid * 8 + (pid % 8);
    int pn = (pid % npg) / 8;
    int bm = pm * GBM, bn = pn * GBN;

    int lrowA = tid >> 2, lchA = tid & 3;
    int lrowB = tid >> 4, lchB = tid & 15;
    const h16* gA = A + (size_t)bm * K;
    const h16* gBn = B + bn;

    uint32_t aoff = (uint32_t)((wm * 64 + (lid & 15)) * RSA + (lid >> 4) * 16);
    uint32_t boff = (uint32_t)((lid & 15) * RSBB + (wn * 32 + ((lid >> 4) << 3)) * 2);

    float acc[4][4][4];
#pragma unroll
    for (int i = 0; i < 4; ++i)
#pragma unroll
        for (int j = 0; j < 4; ++j)
#pragma unroll
            for (int q = 0; q < 4; ++q) acc[i][j][q] = 0.0f;

    int nk = K / BKH;

    auto load = [&](int s) {
        uint32_t base = sb + (uint32_t)(s & 3) * STAGE;
        int k0 = s * BKH;
#pragma unroll
        for (int it = 0; it < 2; ++it) {
            int row = lrowA + it * 128;
            uint32_t so = (uint32_t)(row * RSA + lchA * 16);
            cp16(base + so, gA + (size_t)row * K + k0 + lchA * 8);
        }
        {
            uint32_t so = (uint32_t)(lrowB * RSBB + lchB * 16);
            cp16(base + A_BYTES + so, gBn + (size_t)(k0 + lrowB) * VV + lchB * 8);
        }
    };

#pragma unroll
    for (int i = 0; i < 3; ++i) {
        if (i < nk) load(i);
        asm volatile("cp.async.commit_group;" ::: "memory");
    }

    for (int s = 0; s < nk; ++s) {
        asm volatile("cp.async.wait_group 2;" ::: "memory");
        __syncthreads();
        uint32_t base = sb + (uint32_t)(s & 3) * STAGE;
        uint32_t Ab = base + aoff;
        uint32_t Bb = base + A_BYTES + boff;
#pragma unroll
        for (int tk = 0; tk < 2; ++tk) {
            uint32_t a[4][4], bfr[4][2];
#pragma unroll
            for (int mi = 0; mi < 4; ++mi)
                ldsm4(a[mi][0], a[mi][1], a[mi][2], a[mi][3], Ab + mi * (16 * RSA) + tk * 32);
            {
                uint32_t kbase = Bb + (uint32_t)tk * (16 * RSBB);
                uint32_t t0, t1, t2, t3;
                ldsm4t(t0, t1, t2, t3, kbase);
                bfr[0][0] = t0; bfr[0][1] = t1;
                bfr[1][0] = t2; bfr[1][1] = t3;
                ldsm4t(t0, t1, t2, t3, kbase + 32);
                bfr[2][0] = t0; bfr[2][1] = t1;
                bfr[3][0] = t2; bfr[3][1] = t3;
            }
#pragma unroll
            for (int mi = 0; mi < 4; ++mi)
#pragma unroll
                for (int nj = 0; nj < 4; ++nj) mma16816(acc[mi][nj], a[mi], bfr[nj]);
        }
        if (s + 3 < nk) load(s + 3);
        asm volatile("cp.async.commit_group;" ::: "memory");
    }

    // epilogue
#pragma unroll
    for (int mi = 0; mi < 4; ++mi) {
        int rbase = bm + wm * 64 + mi * 16 + (lid >> 2);
#pragma unroll
        for (int nj = 0; nj < 4; ++nj) {
            int cn = bn + wn * 32 + nj * 8 + (lid & 3) * 2;
            float2 bv = *(const float2*)&bias[cn];
#pragma unroll
            for (int hh = 0; hh < 2; ++hh) {
                int row = rbase + hh * 8;
                size_t o = (size_t)row * VV + cn;
                float v0 = acc[mi][nj][hh * 2 + 0] + bv.x;
                float v1 = acc[mi][nj][hh * 2 + 1] + bv.y;
                if (EPI == 0) {
                    float2 mk = *(const float2*)&mask[o];
                    v0 = fmaxf(v0, 0.0f) * mk.x;
                    v1 = fmaxf(v1, 0.0f) * mk.y;
                    *(__half2*)(outh + o) = __floats2half2_rn(v0, v1);
                } else {
                    float2 rr;
                    rr.x = sigf(v0); rr.y = sigf(v1);
                    *(float2*)(outf + o) = rr;
                }
            }
        }
    }
}

// ---------------- launch (serial, proven ordering) ----------------
extern "C" void kernel_launch(void* const* d_in, const int* in_sizes, int n_in,
                              void* d_out, int out_size) {
    const int*   inp      = (const int*)  d_in[0];
    const float* E        = (const float*)d_in[1];
    const float* Wx       = (const float*)d_in[2];
    const float* U        = (const float*)d_in[3];
    const float* bb       = (const float*)d_in[4];
    const float* W1       = (const float*)d_in[5];
    const float* b1       = (const float*)d_in[6];
    const float* W1b      = (const float*)d_in[7];
    const float* W2       = (const float*)d_in[8];
    const float* b2       = (const float*)d_in[9];
    const float* rec_mask = (const float*)d_in[10];
    const float* dmask1   = (const float*)d_in[11];
    const float* dmask2   = (const float*)d_in[12];
    float* out = (float*)d_out;

    void *p_pooled, *p_w1p, *p_wbh, *p_w2h, *p_x1, *p_x2;
    cudaGetSymbolAddress(&p_pooled, g_pooled);
    cudaGetSymbolAddress(&p_w1p, g_W1p);
    cudaGetSymbolAddress(&p_wbh, g_W1bh);
    cudaGetSymbolAddress(&p_w2h, g_W2h);
    cudaGetSymbolAddress(&p_x1, g_x1);
    cudaGetSymbolAddress(&p_x2, g_x2);

    cudaFuncSetAttribute(hgemm<0>, cudaFuncAttributeMaxDynamicSharedMemorySize, GSMEM);
    cudaFuncSetAttribute(hgemm<1>, cudaFuncAttributeMaxDynamicSharedMemorySize, GSMEM);

    prep_kernel<<<NB_EWX + NB_W1 + 2 * (int)NB_CONV, 256>>>(E, Wx, bb, W1, W1b, W2);
    lstm_kernel<<<BB, 256>>>(inp, U, rec_mask);

    const int grid = (MM / GBM) * (VV / GBN);   // 16 * 64 = 1024
    hgemm<0><<<grid, 512, GSMEM>>>((const h16*)p_pooled, (const h16*)p_w1p, 64,
                                   b1, dmask1, (h16*)p_x1, nullptr);
    hgemm<0><<<grid, 512, GSMEM>>>((const h16*)p_x1, (const h16*)p_wbh, VV,
                                   b1, dmask2, (h16*)p_x2, nullptr);
    hgemm<1><<<grid, 512, GSMEM>>>((const h16*)p_x2, (const h16*)p_w2h, VV,
                                   b2, nullptr, nullptr, out);
}